// round 1
// baseline (speedup 1.0000x reference)
#include <cuda_runtime.h>
#include <cuda_bf16.h>
#include <cstdint>

// Problem constants (fixed by the dataset)
#define MAX_N 50000
#define D 64

// Scratch (allocation-free rule: __device__ globals)
__device__ int   g_deg[MAX_N];
__device__ float g_norm[MAX_N];
__device__ float g_h[(size_t)MAX_N * D];

// ---------------------------------------------------------------------------
// 1) zero degree array
__global__ void zero_deg_kernel(int n) {
    int i = blockIdx.x * blockDim.x + threadIdx.x;
    if (i < n) g_deg[i] = 0;
}

// 2) count in-degree over dst
__global__ void deg_kernel(const int* __restrict__ dst, int e) {
    int i = blockIdx.x * blockDim.x + threadIdx.x;
    if (i < e) atomicAdd(&g_deg[dst[i]], 1);
}

// 3) norm = deg>0 ? rsqrt(deg) : 0
__global__ void norm_kernel(int n) {
    int i = blockIdx.x * blockDim.x + threadIdx.x;
    if (i < n) {
        int d = g_deg[i];
        g_norm[i] = d > 0 ? rsqrtf((float)d) : 0.0f;
    }
}

// 4) h[row] = norm[row] * (x[row] @ W)   -- one warp per row, W in smem
__global__ void gemm_kernel(const float* __restrict__ x,
                            const float* __restrict__ w,
                            int n) {
    __shared__ float Ws[D * D];
    int tid = threadIdx.x;
    for (int i = tid; i < D * D; i += blockDim.x) Ws[i] = w[i];
    __syncthreads();

    int lane = tid & 31;
    int warp = tid >> 5;
    int warps_per_block = blockDim.x >> 5;
    int row0 = blockIdx.x * warps_per_block + warp;
    int stride = gridDim.x * warps_per_block;

    for (int row = row0; row < n; row += stride) {
        const float* xr = x + (size_t)row * D;
        float xv0 = xr[lane];
        float xv1 = xr[lane + 32];
        float a0 = 0.f, a1 = 0.f;
#pragma unroll
        for (int k = 0; k < 32; k++) {
            float xk = __shfl_sync(0xffffffffu, xv0, k);
            a0 = fmaf(xk, Ws[k * D + lane], a0);
            a1 = fmaf(xk, Ws[k * D + lane + 32], a1);
        }
#pragma unroll
        for (int k = 0; k < 32; k++) {
            float xk = __shfl_sync(0xffffffffu, xv1, k);
            a0 = fmaf(xk, Ws[(k + 32) * D + lane], a0);
            a1 = fmaf(xk, Ws[(k + 32) * D + lane + 32], a1);
        }
        float nrm = g_norm[row];
        float* hr = g_h + (size_t)row * D;
        hr[lane]      = a0 * nrm;
        hr[lane + 32] = a1 * nrm;
    }
}

// 5) zero output accumulator (d_out is poisoned with 0xAA by the harness)
__global__ void zero_out_kernel(float4* out, int n4) {
    int i = blockIdx.x * blockDim.x + threadIdx.x;
    if (i < n4) out[i] = make_float4(0.f, 0.f, 0.f, 0.f);
}

// 6) scatter: out[dst] += h[src]   -- 16 threads per edge, one float4 + red.v4 each
__global__ void scatter_kernel(const int* __restrict__ src,
                               const int* __restrict__ dst,
                               float* __restrict__ out,
                               int e) {
    int idx = blockIdx.x * blockDim.x + threadIdx.x;
    int edge = idx >> 4;
    if (edge >= e) return;
    int part = (idx & 15) << 2;          // float offset within the 64-float row
    int s = __ldg(src + edge);
    int d = __ldg(dst + edge);
    float4 v = *reinterpret_cast<const float4*>(g_h + (size_t)s * D + part);
    float* p = out + (size_t)d * D + part;
    asm volatile("red.global.add.v4.f32 [%0], {%1, %2, %3, %4};"
                 :: "l"(p), "f"(v.x), "f"(v.y), "f"(v.z), "f"(v.w)
                 : "memory");
}

// 7) finalize: out = softplus(out * norm[row] + bias[col])
__global__ void finalize_kernel(float* __restrict__ out,
                                const float* __restrict__ bias,
                                int n) {
    __shared__ float bs[D];
    if (threadIdx.x < D) bs[threadIdx.x] = bias[threadIdx.x];
    __syncthreads();
    int i = blockIdx.x * blockDim.x + threadIdx.x;
    int total = n * D;
    if (i < total) {
        int row = i >> 6;       // / D
        int col = i & 63;       // % D
        float v = out[i] * g_norm[row] + bs[col];
        // numerically stable softplus: max(v,0) + log1p(exp(-|v|))
        out[i] = fmaxf(v, 0.f) + log1pf(__expf(-fabsf(v)));
    }
}

// ---------------------------------------------------------------------------
extern "C" void kernel_launch(void* const* d_in, const int* in_sizes, int n_in,
                              void* d_out, int out_size) {
    // inputs: t, x, weight, bias, src, dst
    const float* x    = (const float*)d_in[1];
    const float* w    = (const float*)d_in[2];
    const float* bias = (const float*)d_in[3];
    const int*   src  = (const int*)d_in[4];
    const int*   dst  = (const int*)d_in[5];
    float*       out  = (float*)d_out;

    int n = in_sizes[1] / D;      // 50000
    int e = in_sizes[4];          // 1,600,000

    // 1) zero degree
    zero_deg_kernel<<<(n + 255) / 256, 256>>>(n);
    // 2) count degree
    deg_kernel<<<(e + 255) / 256, 256>>>(dst, e);
    // 3) norm
    norm_kernel<<<(n + 255) / 256, 256>>>(n);
    // 4) h = norm * (x @ W)  (8 warps/block)
    {
        int warps_per_block = 8;
        int blocks = (n + warps_per_block - 1) / warps_per_block;
        gemm_kernel<<<blocks, warps_per_block * 32>>>(x, w, n);
    }
    // 5) zero out
    {
        int n4 = (n * D) / 4;
        zero_out_kernel<<<(n4 + 255) / 256, 256>>>((float4*)out, n4);
    }
    // 6) scatter (16 threads/edge)
    {
        long long threads = (long long)e * 16;
        int blocks = (int)((threads + 255) / 256);
        scatter_kernel<<<blocks, 256>>>(src, dst, out, e);
    }
    // 7) finalize
    finalize_kernel<<<(n * D + 255) / 256, 256>>>(out, bias, n);
}

// round 2
// speedup vs baseline: 1.7142x; 1.7142x over previous
#include <cuda_runtime.h>
#include <cuda_bf16.h>
#include <cstdint>

#define MAX_N 50048
#define MAX_E 1605632
#define D 64

// Scratch (__device__ globals — allocation-free rule)
__device__ int   g_deg[MAX_N];
__device__ float g_norm[MAX_N];
__device__ float g_h[(size_t)MAX_N * D];
__device__ int   g_off[MAX_N + 1];
__device__ int   g_cur[MAX_N];
__device__ int   g_csr[MAX_E];
__device__ int   g_bsum[512];
__device__ int   g_bsumx[512];

// ---------------------------------------------------------------------------
__global__ void zero_deg_kernel(int n) {
    int i = blockIdx.x * blockDim.x + threadIdx.x;
    if (i < n) g_deg[i] = 0;
}

__global__ void deg_kernel(const int* __restrict__ dst, int e) {
    int i = blockIdx.x * blockDim.x + threadIdx.x;
    if (i < e) atomicAdd(&g_deg[dst[i]], 1);
}

// ---------------------------------------------------------------------------
// Exclusive scan of g_deg into g_off (3 kernels), plus norm computation.
__device__ __forceinline__ int warp_incl_scan(int v, int lane) {
#pragma unroll
    for (int o = 1; o < 32; o <<= 1) {
        int t = __shfl_up_sync(0xffffffffu, v, o);
        if (lane >= o) v += t;
    }
    return v;
}

// Block-level scan of 256 elements; writes per-block exclusive scan + block sum.
// Also computes g_norm.
__global__ void scan1_kernel(int n) {
    __shared__ int wsum[8];
    int tid  = threadIdx.x;
    int lane = tid & 31;
    int wid  = tid >> 5;
    int i    = blockIdx.x * 256 + tid;

    int v = (i < n) ? g_deg[i] : 0;
    if (i < n) g_norm[i] = v > 0 ? rsqrtf((float)v) : 0.0f;

    int incl = warp_incl_scan(v, lane);
    if (lane == 31) wsum[wid] = incl;
    __syncthreads();
    if (wid == 0) {
        int wv = (lane < 8) ? wsum[lane] : 0;
        wv = warp_incl_scan(wv, lane);
        if (lane < 8) wsum[lane] = wv;
    }
    __syncthreads();
    int base = (wid > 0) ? wsum[wid - 1] : 0;
    int excl = base + incl - v;
    if (i < n) g_off[i] = excl;
    if (tid == 255) g_bsum[blockIdx.x] = base + incl;
}

// Single block scans the per-block sums (nblocks <= 512).
__global__ void scan2_kernel(int nblocks) {
    __shared__ int wsum[16];
    int tid = threadIdx.x;          // 512 threads
    int lane = tid & 31;
    int wid  = tid >> 5;
    int v = (tid < nblocks) ? g_bsum[tid] : 0;
    int incl = warp_incl_scan(v, lane);
    if (lane == 31) wsum[wid] = incl;
    __syncthreads();
    if (wid == 0) {
        int wv = (lane < 16) ? wsum[lane] : 0;
        wv = warp_incl_scan(wv, lane);
        if (lane < 16) wsum[lane] = wv;
    }
    __syncthreads();
    int base = (wid > 0) ? wsum[wid - 1] : 0;
    if (tid < nblocks) g_bsumx[tid] = base + incl - v;  // exclusive
}

// Add block offsets; init cursor; set sentinel.
__global__ void scan3_kernel(int n, int e) {
    int i = blockIdx.x * blockDim.x + threadIdx.x;
    if (i < n) {
        int o = g_off[i] + g_bsumx[blockIdx.x * 256 / 256 == 0 ? 0 : 0];
        // (note: block size 256 matches scan1 block size)
        o = g_off[i] + g_bsumx[i >> 8];
        g_off[i] = o;
        g_cur[i] = o;
    }
    if (i == 0) g_off[n] = e;
}

// ---------------------------------------------------------------------------
// Fill CSR: csr[pos] = src for edges sorted by dst.
__global__ void fill_kernel(const int* __restrict__ src,
                            const int* __restrict__ dst, int e) {
    int i = blockIdx.x * blockDim.x + threadIdx.x;
    if (i < e) {
        int d = dst[i];
        int pos = atomicAdd(&g_cur[d], 1);
        g_csr[pos] = src[i];
    }
}

// ---------------------------------------------------------------------------
// Register-tiled GEMM: h[row] = norm[row] * (x[row] @ W).
// 64x64 output tile per block, 256 threads (16x16), 4x4 micro-tile.
__global__ __launch_bounds__(256) void gemm_kernel(const float* __restrict__ x,
                                                   const float* __restrict__ w,
                                                   int n) {
    __shared__ float xs[D][D + 1];   // [row][k], padded
    __shared__ float ws[D][D];       // [k][col]

    int tid = threadIdx.x;
    int tx = tid & 15;       // col group
    int ty = tid >> 4;       // row group
    int r0 = blockIdx.x * 64;

    // load x tile (guarded) — coalesced over k
#pragma unroll
    for (int idx = tid; idx < D * D; idx += 256) {
        int row = idx >> 6, k = idx & 63;
        int gr = r0 + row;
        xs[row][k] = (gr < n) ? x[(size_t)gr * D + k] : 0.0f;
    }
    // load W
#pragma unroll
    for (int idx = tid; idx < D * D; idx += 256) {
        ws[idx >> 6][idx & 63] = w[idx];
    }
    __syncthreads();

    float acc[4][4];
#pragma unroll
    for (int i = 0; i < 4; i++)
#pragma unroll
        for (int j = 0; j < 4; j++) acc[i][j] = 0.0f;

#pragma unroll 8
    for (int k = 0; k < D; k++) {
        float a0 = xs[ty * 4 + 0][k];
        float a1 = xs[ty * 4 + 1][k];
        float a2 = xs[ty * 4 + 2][k];
        float a3 = xs[ty * 4 + 3][k];
        float4 b = *reinterpret_cast<const float4*>(&ws[k][tx * 4]);
        acc[0][0] = fmaf(a0, b.x, acc[0][0]); acc[0][1] = fmaf(a0, b.y, acc[0][1]);
        acc[0][2] = fmaf(a0, b.z, acc[0][2]); acc[0][3] = fmaf(a0, b.w, acc[0][3]);
        acc[1][0] = fmaf(a1, b.x, acc[1][0]); acc[1][1] = fmaf(a1, b.y, acc[1][1]);
        acc[1][2] = fmaf(a1, b.z, acc[1][2]); acc[1][3] = fmaf(a1, b.w, acc[1][3]);
        acc[2][0] = fmaf(a2, b.x, acc[2][0]); acc[2][1] = fmaf(a2, b.y, acc[2][1]);
        acc[2][2] = fmaf(a2, b.z, acc[2][2]); acc[2][3] = fmaf(a2, b.w, acc[2][3]);
        acc[3][0] = fmaf(a3, b.x, acc[3][0]); acc[3][1] = fmaf(a3, b.y, acc[3][1]);
        acc[3][2] = fmaf(a3, b.z, acc[3][2]); acc[3][3] = fmaf(a3, b.w, acc[3][3]);
    }

#pragma unroll
    for (int i = 0; i < 4; i++) {
        int row = r0 + ty * 4 + i;
        if (row < n) {
            float nrm = g_norm[row];
            float4 st = make_float4(acc[i][0] * nrm, acc[i][1] * nrm,
                                    acc[i][2] * nrm, acc[i][3] * nrm);
            *reinterpret_cast<float4*>(&g_h[(size_t)row * D + tx * 4]) = st;
        }
    }
}

// ---------------------------------------------------------------------------
// SpMM + finalize: out[node] = softplus(norm[node] * sum_{e in CSR(node)} h[src_e] + bias)
// Half-warp (16 lanes) per node; each lane owns one float4 (16 lanes * 16B = 256B row).
__global__ __launch_bounds__(256) void spmm_kernel(float* __restrict__ out,
                                                   const float* __restrict__ bias,
                                                   int n) {
    int tid = blockIdx.x * blockDim.x + threadIdx.x;
    int node = tid >> 4;
    if (node >= n) return;
    int sub = tid & 15;           // float4 slot within the 64-float row

    int beg = g_off[node];
    int end = g_off[node + 1];

    float4 acc0 = make_float4(0.f, 0.f, 0.f, 0.f);
    float4 acc1 = make_float4(0.f, 0.f, 0.f, 0.f);

    int e = beg;
    for (; e + 1 < end; e += 2) {
        int s0 = __ldg(&g_csr[e]);
        int s1 = __ldg(&g_csr[e + 1]);
        float4 v0 = *reinterpret_cast<const float4*>(&g_h[(size_t)s0 * D + sub * 4]);
        float4 v1 = *reinterpret_cast<const float4*>(&g_h[(size_t)s1 * D + sub * 4]);
        acc0.x += v0.x; acc0.y += v0.y; acc0.z += v0.z; acc0.w += v0.w;
        acc1.x += v1.x; acc1.y += v1.y; acc1.z += v1.z; acc1.w += v1.w;
    }
    if (e < end) {
        int s0 = __ldg(&g_csr[e]);
        float4 v0 = *reinterpret_cast<const float4*>(&g_h[(size_t)s0 * D + sub * 4]);
        acc0.x += v0.x; acc0.y += v0.y; acc0.z += v0.z; acc0.w += v0.w;
    }

    float nrm = g_norm[node];
    float4 b = reinterpret_cast<const float4*>(bias)[sub];
    float4 r;
    r.x = (acc0.x + acc1.x) * nrm + b.x;
    r.y = (acc0.y + acc1.y) * nrm + b.y;
    r.z = (acc0.z + acc1.z) * nrm + b.z;
    r.w = (acc0.w + acc1.w) * nrm + b.w;
    // stable softplus
    r.x = fmaxf(r.x, 0.f) + log1pf(__expf(-fabsf(r.x)));
    r.y = fmaxf(r.y, 0.f) + log1pf(__expf(-fabsf(r.y)));
    r.z = fmaxf(r.z, 0.f) + log1pf(__expf(-fabsf(r.z)));
    r.w = fmaxf(r.w, 0.f) + log1pf(__expf(-fabsf(r.w)));
    *reinterpret_cast<float4*>(&out[(size_t)node * D + sub * 4]) = r;
}

// ---------------------------------------------------------------------------
extern "C" void kernel_launch(void* const* d_in, const int* in_sizes, int n_in,
                              void* d_out, int out_size) {
    // inputs: t, x, weight, bias, src, dst
    const float* x    = (const float*)d_in[1];
    const float* w    = (const float*)d_in[2];
    const float* bias = (const float*)d_in[3];
    const int*   src  = (const int*)d_in[4];
    const int*   dst  = (const int*)d_in[5];
    float*       out  = (float*)d_out;

    int n = in_sizes[1] / D;      // 50000
    int e = in_sizes[4];          // 1,600,000

    int nblocks256 = (n + 255) / 256;   // 196

    zero_deg_kernel<<<nblocks256, 256>>>(n);
    deg_kernel<<<(e + 255) / 256, 256>>>(dst, e);
    scan1_kernel<<<nblocks256, 256>>>(n);
    scan2_kernel<<<1, 512>>>(nblocks256);
    scan3_kernel<<<nblocks256, 256>>>(n, e);
    fill_kernel<<<(e + 255) / 256, 256>>>(src, dst, e);

    gemm_kernel<<<(n + 63) / 64, 256>>>(x, w, n);

    {
        long long threads = (long long)n * 16;
        int blocks = (int)((threads + 255) / 256);
        spmm_kernel<<<blocks, 256>>>(out, bias, n);
    }
}

// round 3
// speedup vs baseline: 1.8045x; 1.0527x over previous
#include <cuda_runtime.h>
#include <cuda_fp16.h>
#include <cstdint>

#define MAX_N 50048
#define MAX_E 1605632
#define D 64

// Scratch (__device__ globals — allocation-free rule)
__device__ int   g_deg[MAX_N];
__device__ float g_norm[MAX_N];
__device__ uint4 g_h16[(size_t)MAX_N * 8];   // fp16 h: 64 halves = 8 uint4 per row
__device__ int   g_off[MAX_N + 1];
__device__ int   g_cur[MAX_N];
__device__ int   g_csr[MAX_E];
__device__ int   g_bsum[512];

// ---------------------------------------------------------------------------
__global__ void zero_deg_kernel(int n) {
    int i = blockIdx.x * blockDim.x + threadIdx.x;
    if (i < n) g_deg[i] = 0;
}

// count in-degree; int4-vectorized dst reads
__global__ void deg_kernel(const int* __restrict__ dst, int e) {
    int i = blockIdx.x * blockDim.x + threadIdx.x;
    int base = i * 4;
    if (base + 3 < e) {
        int4 d = *reinterpret_cast<const int4*>(dst + base);
        atomicAdd(&g_deg[d.x], 1);
        atomicAdd(&g_deg[d.y], 1);
        atomicAdd(&g_deg[d.z], 1);
        atomicAdd(&g_deg[d.w], 1);
    } else {
        for (int j = base; j < e; j++) atomicAdd(&g_deg[dst[j]], 1);
    }
}

// ---------------------------------------------------------------------------
__device__ __forceinline__ int warp_incl_scan(int v, int lane) {
#pragma unroll
    for (int o = 1; o < 32; o <<= 1) {
        int t = __shfl_up_sync(0xffffffffu, v, o);
        if (lane >= o) v += t;
    }
    return v;
}

// Per-block exclusive scan of deg -> g_off (local); block sums -> g_bsum; norm.
__global__ void scan1_kernel(int n) {
    __shared__ int wsum[8];
    int tid  = threadIdx.x;
    int lane = tid & 31;
    int wid  = tid >> 5;
    int i    = blockIdx.x * 256 + tid;

    int v = (i < n) ? g_deg[i] : 0;
    if (i < n) g_norm[i] = v > 0 ? rsqrtf((float)v) : 0.0f;

    int incl = warp_incl_scan(v, lane);
    if (lane == 31) wsum[wid] = incl;
    __syncthreads();
    if (wid == 0) {
        int wv = (lane < 8) ? wsum[lane] : 0;
        wv = warp_incl_scan(wv, lane);
        if (lane < 8) wsum[lane] = wv;
    }
    __syncthreads();
    int base = (wid > 0) ? wsum[wid - 1] : 0;
    if (i < n) g_off[i] = base + incl - v;
    if (tid == 255) g_bsum[blockIdx.x] = base + incl;
}

// Fused scan2+scan3: each block reduces its prefix of block sums, applies
// offset, inits cursor, sets sentinel. nblocks <= 256.
__global__ void scan23_kernel(int n, int e, int nblocks) {
    __shared__ int wsum[8];
    __shared__ int base_s;
    int tid  = threadIdx.x;
    int lane = tid & 31;
    int wid  = tid >> 5;

    int v = (tid < nblocks && tid < blockIdx.x) ? g_bsum[tid] : 0;
#pragma unroll
    for (int o = 16; o; o >>= 1) v += __shfl_down_sync(0xffffffffu, v, o);
    if (lane == 0) wsum[wid] = v;
    __syncthreads();
    if (tid == 0) {
        int s = 0;
#pragma unroll
        for (int j = 0; j < 8; j++) s += wsum[j];
        base_s = s;
    }
    __syncthreads();

    int i = blockIdx.x * 256 + tid;
    if (i < n) {
        int o = g_off[i] + base_s;
        g_off[i] = o;
        g_cur[i] = o;
    }
    if (i == 0) g_off[n] = e;
}

// ---------------------------------------------------------------------------
// Fill CSR: csr[pos] = src for edges bucketed by dst.
__global__ void fill_kernel(const int* __restrict__ src,
                            const int* __restrict__ dst, int e) {
    int i = blockIdx.x * blockDim.x + threadIdx.x;
    if (i < e) {
        int d = dst[i];
        int pos = atomicAdd(&g_cur[d], 1);
        g_csr[pos] = src[i];
    }
}

// ---------------------------------------------------------------------------
// Register-tiled GEMM: h16[row] = fp16(norm[row] * (x[row] @ W)).
__global__ __launch_bounds__(256) void gemm_kernel(const float* __restrict__ x,
                                                   const float* __restrict__ w,
                                                   int n) {
    __shared__ float xs[D][D + 1];
    __shared__ float ws[D][D];

    int tid = threadIdx.x;
    int tx = tid & 15;
    int ty = tid >> 4;
    int r0 = blockIdx.x * 64;

#pragma unroll
    for (int idx = tid; idx < D * D; idx += 256) {
        int row = idx >> 6, k = idx & 63;
        int gr = r0 + row;
        xs[row][k] = (gr < n) ? x[(size_t)gr * D + k] : 0.0f;
    }
#pragma unroll
    for (int idx = tid; idx < D * D; idx += 256) {
        ws[idx >> 6][idx & 63] = w[idx];
    }
    __syncthreads();

    float acc[4][4];
#pragma unroll
    for (int i = 0; i < 4; i++)
#pragma unroll
        for (int j = 0; j < 4; j++) acc[i][j] = 0.0f;

#pragma unroll 8
    for (int k = 0; k < D; k++) {
        float a0 = xs[ty * 4 + 0][k];
        float a1 = xs[ty * 4 + 1][k];
        float a2 = xs[ty * 4 + 2][k];
        float a3 = xs[ty * 4 + 3][k];
        float4 b = *reinterpret_cast<const float4*>(&ws[k][tx * 4]);
        acc[0][0] = fmaf(a0, b.x, acc[0][0]); acc[0][1] = fmaf(a0, b.y, acc[0][1]);
        acc[0][2] = fmaf(a0, b.z, acc[0][2]); acc[0][3] = fmaf(a0, b.w, acc[0][3]);
        acc[1][0] = fmaf(a1, b.x, acc[1][0]); acc[1][1] = fmaf(a1, b.y, acc[1][1]);
        acc[1][2] = fmaf(a1, b.z, acc[1][2]); acc[1][3] = fmaf(a1, b.w, acc[1][3]);
        acc[2][0] = fmaf(a2, b.x, acc[2][0]); acc[2][1] = fmaf(a2, b.y, acc[2][1]);
        acc[2][2] = fmaf(a2, b.z, acc[2][2]); acc[2][3] = fmaf(a2, b.w, acc[2][3]);
        acc[3][0] = fmaf(a3, b.x, acc[3][0]); acc[3][1] = fmaf(a3, b.y, acc[3][1]);
        acc[3][2] = fmaf(a3, b.z, acc[3][2]); acc[3][3] = fmaf(a3, b.w, acc[3][3]);
    }

    uint2* hbase = reinterpret_cast<uint2*>(g_h16);
#pragma unroll
    for (int i = 0; i < 4; i++) {
        int row = r0 + ty * 4 + i;
        if (row < n) {
            float nrm = g_norm[row];
            __half2 h01 = __floats2half2_rn(acc[i][0] * nrm, acc[i][1] * nrm);
            __half2 h23 = __floats2half2_rn(acc[i][2] * nrm, acc[i][3] * nrm);
            uint2 st;
            st.x = *reinterpret_cast<unsigned*>(&h01);
            st.y = *reinterpret_cast<unsigned*>(&h23);
            hbase[(size_t)row * 16 + tx] = st;   // 8B per (row, tx) slot
        }
    }
}

// ---------------------------------------------------------------------------
// SpMM + finalize, fp16 gather, fp32 accumulate.
// 8 lanes per node; each lane owns one uint4 (8 halves = 16B of the 128B row).
__global__ __launch_bounds__(256) void spmm_kernel(float* __restrict__ out,
                                                   const float* __restrict__ bias,
                                                   int n) {
    int tid = blockIdx.x * blockDim.x + threadIdx.x;
    int node = tid >> 3;
    if (node >= n) return;
    int sub = tid & 7;

    int beg = g_off[node];
    int end = g_off[node + 1];

    float2 a0 = make_float2(0.f, 0.f), a1 = a0, a2 = a0, a3 = a0;
    float2 b0 = a0, b1 = a0, b2 = a0, b3 = a0;

    const uint4* hbase = g_h16;
    int e = beg;
    for (; e + 1 < end; e += 2) {
        int s0 = __ldg(&g_csr[e]);
        int s1 = __ldg(&g_csr[e + 1]);
        uint4 v0 = __ldg(&hbase[(size_t)s0 * 8 + sub]);
        uint4 v1 = __ldg(&hbase[(size_t)s1 * 8 + sub]);
        __half2 h;
        float2 f;
        *reinterpret_cast<unsigned*>(&h) = v0.x; f = __half22float2(h); a0.x += f.x; a0.y += f.y;
        *reinterpret_cast<unsigned*>(&h) = v0.y; f = __half22float2(h); a1.x += f.x; a1.y += f.y;
        *reinterpret_cast<unsigned*>(&h) = v0.z; f = __half22float2(h); a2.x += f.x; a2.y += f.y;
        *reinterpret_cast<unsigned*>(&h) = v0.w; f = __half22float2(h); a3.x += f.x; a3.y += f.y;
        *reinterpret_cast<unsigned*>(&h) = v1.x; f = __half22float2(h); b0.x += f.x; b0.y += f.y;
        *reinterpret_cast<unsigned*>(&h) = v1.y; f = __half22float2(h); b1.x += f.x; b1.y += f.y;
        *reinterpret_cast<unsigned*>(&h) = v1.z; f = __half22float2(h); b2.x += f.x; b2.y += f.y;
        *reinterpret_cast<unsigned*>(&h) = v1.w; f = __half22float2(h); b3.x += f.x; b3.y += f.y;
    }
    if (e < end) {
        int s0 = __ldg(&g_csr[e]);
        uint4 v0 = __ldg(&hbase[(size_t)s0 * 8 + sub]);
        __half2 h;
        float2 f;
        *reinterpret_cast<unsigned*>(&h) = v0.x; f = __half22float2(h); a0.x += f.x; a0.y += f.y;
        *reinterpret_cast<unsigned*>(&h) = v0.y; f = __half22float2(h); a1.x += f.x; a1.y += f.y;
        *reinterpret_cast<unsigned*>(&h) = v0.z; f = __half22float2(h); a2.x += f.x; a2.y += f.y;
        *reinterpret_cast<unsigned*>(&h) = v0.w; f = __half22float2(h); a3.x += f.x; a3.y += f.y;
    }

    a0.x += b0.x; a0.y += b0.y; a1.x += b1.x; a1.y += b1.y;
    a2.x += b2.x; a2.y += b2.y; a3.x += b3.x; a3.y += b3.y;

    float nrm = g_norm[node];
    float4 bv0 = reinterpret_cast<const float4*>(bias)[sub * 2];
    float4 bv1 = reinterpret_cast<const float4*>(bias)[sub * 2 + 1];

    float r[8];
    r[0] = a0.x * nrm + bv0.x; r[1] = a0.y * nrm + bv0.y;
    r[2] = a1.x * nrm + bv0.z; r[3] = a1.y * nrm + bv0.w;
    r[4] = a2.x * nrm + bv1.x; r[5] = a2.y * nrm + bv1.y;
    r[6] = a3.x * nrm + bv1.z; r[7] = a3.y * nrm + bv1.w;
#pragma unroll
    for (int j = 0; j < 8; j++)
        r[j] = fmaxf(r[j], 0.f) + log1pf(__expf(-fabsf(r[j])));

    float4* op = reinterpret_cast<float4*>(out + (size_t)node * D + sub * 8);
    op[0] = make_float4(r[0], r[1], r[2], r[3]);
    op[1] = make_float4(r[4], r[5], r[6], r[7]);
}

// ---------------------------------------------------------------------------
extern "C" void kernel_launch(void* const* d_in, const int* in_sizes, int n_in,
                              void* d_out, int out_size) {
    // inputs: t, x, weight, bias, src, dst
    const float* x    = (const float*)d_in[1];
    const float* w    = (const float*)d_in[2];
    const float* bias = (const float*)d_in[3];
    const int*   src  = (const int*)d_in[4];
    const int*   dst  = (const int*)d_in[5];
    float*       out  = (float*)d_out;

    int n = in_sizes[1] / D;      // 50000
    int e = in_sizes[4];          // 1,600,000

    int nblocks256 = (n + 255) / 256;   // 196

    zero_deg_kernel<<<nblocks256, 256>>>(n);
    {
        int quads = (e + 3) / 4;
        deg_kernel<<<(quads + 255) / 256, 256>>>(dst, e);
    }
    scan1_kernel<<<nblocks256, 256>>>(n);
    scan23_kernel<<<nblocks256, 256>>>(n, e, nblocks256);
    fill_kernel<<<(e + 255) / 256, 256>>>(src, dst, e);

    gemm_kernel<<<(n + 63) / 64, 256>>>(x, w, n);

    {
        long long threads = (long long)n * 8;
        int blocks = (int)((threads + 255) / 256);
        spmm_kernel<<<blocks, 256>>>(out, bias, n);
    }
}